// round 1
// baseline (speedup 1.0000x reference)
#include <cuda_runtime.h>

// Problem constants
#define BB 4
#define TT 1024
#define EE 1024
#define HH 16
#define HD 64
#define MULT 2
#define SS (TT*MULT)
static constexpr float QSCALE = 0.125f;  // HD^-0.5

// Scratch (allocation-free rule: __device__ globals)
__device__ float g_Q[BB*TT*EE];     // [B,T,E]  scaled q
__device__ float g_K[BB*SS*EE];     // [B,T,2E] == [B,S,E]
__device__ float g_V[BB*SS*EE];
__device__ float g_AO[BB*TT*EE];    // attention output [B,T,E]

// ---------------------------------------------------------------------------
// SGEMM: C[m,n] = (sum_k A[m,k]*W[n,k] + bias[n]) * scale
// A: [M,K] row-major, W: [N,K] row-major. Tiles 128x128x8, 256 threads.
// M from gridDim.y*128, N/K passed in. All dims divide tiles exactly.
// ---------------------------------------------------------------------------
__global__ __launch_bounds__(256) void sgemm_bias(
    const float* __restrict__ A, const float* __restrict__ W,
    const float* __restrict__ bias, float* __restrict__ C,
    int N, int K, float scale)
{
    __shared__ float As[8][128];
    __shared__ float Bs[8][128];

    const int tid = threadIdx.x;
    const int m0 = blockIdx.y * 128;
    const int n0 = blockIdx.x * 128;

    const int lr = tid >> 1;          // 0..127
    const int lc = (tid & 1) * 4;     // 0 or 4
    const float* Aptr = A + (size_t)(m0 + lr) * K + lc;
    const float* Wptr = W + (size_t)(n0 + lr) * K + lc;

    const int ty = tid >> 4;          // 0..15  (m sub-tile)
    const int tx = tid & 15;          // 0..15  (n sub-tile)

    float acc[8][8];
#pragma unroll
    for (int i = 0; i < 8; i++)
#pragma unroll
        for (int j = 0; j < 8; j++) acc[i][j] = 0.f;

    for (int k0 = 0; k0 < K; k0 += 8) {
        float4 av = *(const float4*)(Aptr + k0);
        float4 wv = *(const float4*)(Wptr + k0);
        As[lc+0][lr] = av.x; As[lc+1][lr] = av.y;
        As[lc+2][lr] = av.z; As[lc+3][lr] = av.w;
        Bs[lc+0][lr] = wv.x; Bs[lc+1][lr] = wv.y;
        Bs[lc+2][lr] = wv.z; Bs[lc+3][lr] = wv.w;
        __syncthreads();

#pragma unroll
        for (int kk = 0; kk < 8; kk++) {
            float a[8], b[8];
            *(float4*)(a)   = *(const float4*)&As[kk][ty*8];
            *(float4*)(a+4) = *(const float4*)&As[kk][ty*8+4];
            *(float4*)(b)   = *(const float4*)&Bs[kk][tx*8];
            *(float4*)(b+4) = *(const float4*)&Bs[kk][tx*8+4];
#pragma unroll
            for (int i = 0; i < 8; i++)
#pragma unroll
                for (int j = 0; j < 8; j++)
                    acc[i][j] = fmaf(a[i], b[j], acc[i][j]);
        }
        __syncthreads();
    }

    float bv[8];
#pragma unroll
    for (int j = 0; j < 8; j++) bv[j] = bias[n0 + tx*8 + j];

#pragma unroll
    for (int i = 0; i < 8; i++) {
        const int m = m0 + ty*8 + i;
        float* crow = C + (size_t)m * N + n0 + tx*8;
        float4 o0, o1;
        o0.x = (acc[i][0] + bv[0]) * scale;
        o0.y = (acc[i][1] + bv[1]) * scale;
        o0.z = (acc[i][2] + bv[2]) * scale;
        o0.w = (acc[i][3] + bv[3]) * scale;
        o1.x = (acc[i][4] + bv[4]) * scale;
        o1.y = (acc[i][5] + bv[5]) * scale;
        o1.z = (acc[i][6] + bv[6]) * scale;
        o1.w = (acc[i][7] + bv[7]) * scale;
        *(float4*)(crow)     = o0;
        *(float4*)(crow + 4) = o1;
    }
}

// ---------------------------------------------------------------------------
// Flash attention, fp32, online softmax.
// grid: (T/64, H, B), 256 threads.
// Q tile 64 queries x 64 dims; key tiles of 32; mask pre-loaded into Ss.
// Output written in [B,T,H*HD] layout directly (== transpose+reshape).
// ---------------------------------------------------------------------------
__global__ __launch_bounds__(256) void flash_attn(
    const float* __restrict__ Q, const float* __restrict__ K,
    const float* __restrict__ V, const float* __restrict__ mask,
    float* __restrict__ O)
{
    __shared__ float Qs[64][64];
    __shared__ float Ks[32][68];
    __shared__ float Vs[32][68];
    __shared__ float Ssm[64][36];
    __shared__ float alpha_s[64];
    __shared__ float l_s[64];

    const int tid = threadIdx.x;
    const int t0 = blockIdx.x * 64;
    const int h  = blockIdx.y;
    const int b  = blockIdx.z;

    // acc mapping: q rows uy*4.., dims ux*4..
    const int uy = tid >> 4, ux = tid & 15;
    // qk mapping: q rows sy*2.., key cols sx*4..
    const int sy = tid >> 3, sx = tid & 7;
    // softmax mapping: row rrow, elems rp*8..rp*8+7
    const int rrow = tid >> 2, rp = tid & 3;

    // Load Q tile
    {
        const float* qbase = Q + ((size_t)(b*TT + t0)) * EE + h*HD;
        for (int fi = tid; fi < 1024; fi += 256) {
            int qi = fi >> 4, dg = (fi & 15) << 2;
            *(float4*)&Qs[qi][dg] = *(const float4*)(qbase + (size_t)qi*EE + dg);
        }
    }

    float acc[4][4];
#pragma unroll
    for (int i = 0; i < 4; i++)
#pragma unroll
        for (int j = 0; j < 4; j++) acc[i][j] = 0.f;
    float m_old = -1e30f, lsum_run = 0.f;

    const float* kb = K + (size_t)b * SS * EE + h*HD;
    const float* vb = V + (size_t)b * SS * EE + h*HD;
    const float* mb = mask + ((size_t)(b*TT + t0)) * TT;

    for (int st = 0; st < SS/32; st++) {
        const int s_base = st * 32;
        const int s0_base = s_base & (TT - 1);   // s mod T for mask indexing

        // K/V tiles: 32x64 = 512 float4
        for (int fi = tid; fi < 512; fi += 256) {
            int sj = fi >> 4, dg = (fi & 15) << 2;
            *(float4*)&Ks[sj][dg] = *(const float4*)(kb + (size_t)(s_base+sj)*EE + dg);
            *(float4*)&Vs[sj][dg] = *(const float4*)(vb + (size_t)(s_base+sj)*EE + dg);
        }
        // mask tile into Ssm: 64x32
        for (int fi = tid; fi < 512; fi += 256) {
            int qi = fi >> 3, sg = (fi & 7) << 2;
            float4 mv = *(const float4*)(mb + (size_t)qi*TT + s0_base + sg);
            Ssm[qi][sg+0] = mv.x; Ssm[qi][sg+1] = mv.y;
            Ssm[qi][sg+2] = mv.z; Ssm[qi][sg+3] = mv.w;
        }
        __syncthreads();

        // S = Q K^T + mask
        {
            float qk[2][4];
#pragma unroll
            for (int i = 0; i < 2; i++)
#pragma unroll
                for (int j = 0; j < 4; j++) qk[i][j] = 0.f;
#pragma unroll
            for (int d4 = 0; d4 < 16; d4++) {
                float4 q0 = *(const float4*)&Qs[sy*2+0][d4*4];
                float4 q1 = *(const float4*)&Qs[sy*2+1][d4*4];
                float4 k0 = *(const float4*)&Ks[sx*4+0][d4*4];
                float4 k1 = *(const float4*)&Ks[sx*4+1][d4*4];
                float4 k2 = *(const float4*)&Ks[sx*4+2][d4*4];
                float4 k3 = *(const float4*)&Ks[sx*4+3][d4*4];
#define DOT4(ac, qv, kv) ac = fmaf(qv.x,kv.x, fmaf(qv.y,kv.y, fmaf(qv.z,kv.z, fmaf(qv.w,kv.w, ac))))
                DOT4(qk[0][0], q0, k0); DOT4(qk[0][1], q0, k1);
                DOT4(qk[0][2], q0, k2); DOT4(qk[0][3], q0, k3);
                DOT4(qk[1][0], q1, k0); DOT4(qk[1][1], q1, k1);
                DOT4(qk[1][2], q1, k2); DOT4(qk[1][3], q1, k3);
#undef DOT4
            }
#pragma unroll
            for (int i = 0; i < 2; i++)
#pragma unroll
                for (int j = 0; j < 4; j++)
                    Ssm[sy*2+i][sx*4+j] += qk[i][j];
        }
        __syncthreads();

        // online softmax (4 threads per row)
        {
            float lm = -1e30f;
#pragma unroll
            for (int j = 0; j < 8; j++) lm = fmaxf(lm, Ssm[rrow][rp*8+j]);
            lm = fmaxf(lm, __shfl_xor_sync(0xffffffffu, lm, 1));
            lm = fmaxf(lm, __shfl_xor_sync(0xffffffffu, lm, 2));
            float m_new = fmaxf(m_old, lm);
            float a = __expf(m_old - m_new);
            float ls = 0.f;
#pragma unroll
            for (int j = 0; j < 8; j++) {
                float p = __expf(Ssm[rrow][rp*8+j] - m_new);
                Ssm[rrow][rp*8+j] = p;
                ls += p;
            }
            ls += __shfl_xor_sync(0xffffffffu, ls, 1);
            ls += __shfl_xor_sync(0xffffffffu, ls, 2);
            lsum_run = lsum_run * a + ls;
            m_old = m_new;
            if (rp == 0) alpha_s[rrow] = a;
        }
        __syncthreads();

        // acc = acc*alpha + P V
        {
#pragma unroll
            for (int i = 0; i < 4; i++) {
                float a = alpha_s[uy*4+i];
#pragma unroll
                for (int j = 0; j < 4; j++) acc[i][j] *= a;
            }
#pragma unroll
            for (int s = 0; s < 32; s++) {
                float4 vv = *(const float4*)&Vs[s][ux*4];
                float p0 = Ssm[uy*4+0][s];
                float p1 = Ssm[uy*4+1][s];
                float p2 = Ssm[uy*4+2][s];
                float p3 = Ssm[uy*4+3][s];
                acc[0][0] = fmaf(p0, vv.x, acc[0][0]);
                acc[0][1] = fmaf(p0, vv.y, acc[0][1]);
                acc[0][2] = fmaf(p0, vv.z, acc[0][2]);
                acc[0][3] = fmaf(p0, vv.w, acc[0][3]);
                acc[1][0] = fmaf(p1, vv.x, acc[1][0]);
                acc[1][1] = fmaf(p1, vv.y, acc[1][1]);
                acc[1][2] = fmaf(p1, vv.z, acc[1][2]);
                acc[1][3] = fmaf(p1, vv.w, acc[1][3]);
                acc[2][0] = fmaf(p2, vv.x, acc[2][0]);
                acc[2][1] = fmaf(p2, vv.y, acc[2][1]);
                acc[2][2] = fmaf(p2, vv.z, acc[2][2]);
                acc[2][3] = fmaf(p2, vv.w, acc[2][3]);
                acc[3][0] = fmaf(p3, vv.x, acc[3][0]);
                acc[3][1] = fmaf(p3, vv.y, acc[3][1]);
                acc[3][2] = fmaf(p3, vv.z, acc[3][2]);
                acc[3][3] = fmaf(p3, vv.w, acc[3][3]);
            }
        }
        __syncthreads();
    }

    if (rp == 0) l_s[rrow] = lsum_run;
    __syncthreads();

    // write output: O[b, t0+q, h*HD + d]
    {
        float* ob = O + ((size_t)(b*TT + t0)) * EE + h*HD;
#pragma unroll
        for (int i = 0; i < 4; i++) {
            int q = uy*4 + i;
            float inv = 1.f / l_s[q];
            float4 o;
            o.x = acc[i][0] * inv;
            o.y = acc[i][1] * inv;
            o.z = acc[i][2] * inv;
            o.w = acc[i][3] * inv;
            *(float4*)(ob + (size_t)q*EE + ux*4) = o;
        }
    }
}

// ---------------------------------------------------------------------------
extern "C" void kernel_launch(void* const* d_in, const int* in_sizes, int n_in,
                              void* d_out, int out_size) {
    const float* x    = (const float*)d_in[0];
    const float* mask = (const float*)d_in[1];
    const float* Wq   = (const float*)d_in[2];
    const float* bq   = (const float*)d_in[3];
    const float* Wk   = (const float*)d_in[4];
    const float* bk   = (const float*)d_in[5];
    const float* Wv   = (const float*)d_in[6];
    const float* bv   = (const float*)d_in[7];
    const float* Wo   = (const float*)d_in[8];
    const float* bo   = (const float*)d_in[9];
    float* out = (float*)d_out;

    float *Qp, *Kp, *Vp, *AOp;
    cudaGetSymbolAddress((void**)&Qp, g_Q);
    cudaGetSymbolAddress((void**)&Kp, g_K);
    cudaGetSymbolAddress((void**)&Vp, g_V);
    cudaGetSymbolAddress((void**)&AOp, g_AO);

    dim3 blk(256);
    // Q = (x Wq^T + bq) * scale     [4096 x 1024]
    sgemm_bias<<<dim3(EE/128, (BB*TT)/128), blk>>>(x, Wq, bq, Qp, EE, EE, QSCALE);
    // K = x Wk^T + bk               [4096 x 2048]
    sgemm_bias<<<dim3((MULT*EE)/128, (BB*TT)/128), blk>>>(x, Wk, bk, Kp, MULT*EE, EE, 1.f);
    // V = x Wv^T + bv               [4096 x 2048]
    sgemm_bias<<<dim3((MULT*EE)/128, (BB*TT)/128), blk>>>(x, Wv, bv, Vp, MULT*EE, EE, 1.f);
    // flash attention -> g_AO [B,T,E]
    flash_attn<<<dim3(TT/64, HH, BB), blk>>>(Qp, Kp, Vp, mask, AOp);
    // out = AO Wo^T + bo            [4096 x 1024]
    sgemm_bias<<<dim3(EE/128, (BB*TT)/128), blk>>>(AOp, Wo, bo, out, EE, EE, 1.f);
}